// round 1
// baseline (speedup 1.0000x reference)
#include <cuda_runtime.h>

#define SQRT_2PI 2.5066282746310002f
#define DCUT 16
#define FDIM 1024

// sum_{d in valid window} exp(-a*d^2), window = [-f, FDIM-1-f] intersect [-DCUT, DCUT]
__device__ __forceinline__ float gauss_window_sum(float a, int f) {
    // s = exp(-a); term_d = exp(-a d^2) via term_{d+1} = term_d * m, m_{d+1} = m * s^2
    float e1 = __expf(-a);
    float e2 = e1 * e1;
    float m = e1, term = e1, sum = 1.0f;
    int fr = FDIM - 1 - f;
    if (f >= DCUT && fr >= DCUT) {
        // interior fast path: symmetric, both sides always valid
        #pragma unroll
        for (int d = 1; d <= DCUT; ++d) {
            sum = fmaf(2.0f, term, sum);
            m *= e2;
            term *= m;
        }
    } else {
        // edge path: count how many sides (0/1/2) include offset d
        #pragma unroll
        for (int d = 1; d <= DCUT; ++d) {
            float c = (d <= f ? 1.0f : 0.0f) + (d <= fr ? 1.0f : 0.0f);
            sum = fmaf(c, term, sum);
            m *= e2;
            term *= m;
        }
    }
    return sum;
}

__global__ void GaussianWrong_kernel(const float4* __restrict__ x,
                                     const float4* __restrict__ sigma,
                                     float4* __restrict__ out,
                                     int n4) {
    int i = blockIdx.x * blockDim.x + threadIdx.x;
    if (i >= n4) return;

    float4 xv = x[i];
    float4 sv = sigma[i];
    int f0 = (i * 4) & (FDIM - 1);  // FDIM divisible by 4, so the vec4 never wraps rows

    float xs[4] = {xv.x, xv.y, xv.z, xv.w};
    float ss[4] = {sv.x, sv.y, sv.z, sv.w};
    float os[4];

    #pragma unroll
    for (int k = 0; k < 4; ++k) {
        float s = ss[k];
        float a = 0.5f / (s * s);
        float sum = gauss_window_sum(a, f0 + k);
        // out = x * sum / (s * sqrt(2*pi))
        os[k] = xs[k] * __fdividef(sum, s * SQRT_2PI);
    }

    float4 ov = make_float4(os[0], os[1], os[2], os[3]);
    out[i] = ov;
}

extern "C" void kernel_launch(void* const* d_in, const int* in_sizes, int n_in,
                              void* d_out, int out_size) {
    const float* x     = (const float*)d_in[0];
    const float* sigma = (const float*)d_in[1];
    float* out = (float*)d_out;

    int n = in_sizes[0];       // B*L*F = 262144
    int n4 = n / 4;
    int tpb = 256;
    int blocks = (n4 + tpb - 1) / tpb;
    GaussianWrong_kernel<<<blocks, tpb>>>((const float4*)x, (const float4*)sigma,
                                          (float4*)out, n4);
}

// round 2
// speedup vs baseline: 1.0539x; 1.0539x over previous
#include <cuda_runtime.h>

#define INV_SQRT_2PI 0.3989422804014327f
#define DCUT 10
#define FDIM 1024

__global__ void GaussianWrong_kernel(const float* __restrict__ x,
                                     const float* __restrict__ sigma,
                                     float* __restrict__ out,
                                     int n) {
    int i = blockIdx.x * blockDim.x + threadIdx.x;
    if (i >= n) return;

    float s  = sigma[i];
    float xv = x[i];

    float inv_s = __fdividef(1.0f, s);
    float a = 0.5f * inv_s * inv_s;            // 1/(2 sigma^2), in [0.08, 2.0]

    // Power tree: E_k = exp(-a)^k via 6 serial squarings, then each
    // term exp(-a*d^2) is a short product of independent powers.
    float E1  = __expf(-a);
    float E2  = E1  * E1;
    float E4  = E2  * E2;
    float E8  = E4  * E4;
    float E16 = E8  * E8;
    float E32 = E16 * E16;
    float E64 = E32 * E32;

    // helper products
    float E48 = E32 * E16;
    float E80 = E64 * E16;
    float E96 = E64 * E32;

    // terms t_d = exp(-a * d*d), d = 1..10   (d^2: 1,4,9,16,25,36,49,64,81,100)
    float t1  = E1;
    float t2  = E4;
    float t3  = E8  * E1;     // 9
    float t4  = E16;
    float t5  = E16 * t3;     // 25 = 16+9
    float t6  = E32 * E4;     // 36
    float t7  = E48 * E1;     // 49
    float t8  = E64;
    float t9  = E80 * E1;     // 81
    float t10 = E96 * E4;     // 100

    int f  = i & (FDIM - 1);
    int fr = (FDIM - 1) - f;

    float sum;
    if (min(f, fr) >= DCUT) {
        // interior: both sides fully inside the row
        float S = (((t1 + t2) + (t3 + t4)) + ((t5 + t6) + (t7 + t8))) + (t9 + t10);
        sum = fmaf(2.0f, S, 1.0f);
    } else {
        // edge: per-offset side count c_d in {0,1,2}
        float S = 0.0f;
        #pragma unroll
        for (int d = 1; d <= DCUT; ++d) {
            float td = (d == 1) ? t1 : (d == 2) ? t2 : (d == 3) ? t3 : (d == 4) ? t4 :
                       (d == 5) ? t5 : (d == 6) ? t6 : (d == 7) ? t7 : (d == 8) ? t8 :
                       (d == 9) ? t9 : t10;
            float c = (float)((d <= f) + (d <= fr));
            S = fmaf(c, td, S);
        }
        sum = S + 1.0f;
    }

    out[i] = xv * sum * inv_s * INV_SQRT_2PI;
}

extern "C" void kernel_launch(void* const* d_in, const int* in_sizes, int n_in,
                              void* d_out, int out_size) {
    const float* x     = (const float*)d_in[0];
    const float* sigma = (const float*)d_in[1];
    float* out = (float*)d_out;

    int n = in_sizes[0];   // B*L*F = 262144
    int tpb = 256;
    int blocks = (n + tpb - 1) / tpb;
    GaussianWrong_kernel<<<blocks, tpb>>>(x, sigma, out, n);
}